// round 9
// baseline (speedup 1.0000x reference)
#include <cuda_runtime.h>
#include <cuda_fp16.h>
#include <math.h>

// Problem constants
#define BB 8
#define TT 2048
#define CC 1024
#define DD 64
#define MM (BB*TT)          // 16384 rows

// ---------------------------------------------------------------------------
// Global scratch (allocation-free __device__)
// fp16 A-frag (m16k16, 128 u32/tile); B-frag (k16n8, 64 u32/tile)
// ---------------------------------------------------------------------------
__device__ unsigned g_qf [MM*DD/2];   // q,  A-frag per 64-token block (scale*log2e folded)
__device__ unsigned g_kf [MM*DD/2];   // k,  B-frag: [tb][(keyTile8)(dTile4)][64]   (k=d,n=key)
__device__ unsigned g_vf [MM*DD/2];   // v,  B-frag: [tb][(dTile8)(keyTile4)][64]   (k=key,n=d)
__device__ unsigned g_wpef[DD*CC/2];      // Wp_eff: [nt(128)][kt(4)][64]
__device__ unsigned g_wqkvf[3*CC*DD/2];   // W q|k|v: [ktG(64)][mat*8+nt(24)][64]
// attention kv-split partials (fp32), A-frag slot layout: float2 per u32 slot
__device__ float2 g_op0[MM*32];       // kv-half 0 O partial (4 MB)
__device__ float2 g_op1[MM*32];       // kv-half 1 O partial (4 MB)
__device__ float  g_lp0[MM];          // kv-half 0 l partial
__device__ float  g_lp1[MM];          // kv-half 1 l partial

// ---------------------------------------------------------------------------
// helpers
// ---------------------------------------------------------------------------
__device__ __forceinline__ unsigned f2h2(float a, float b) {
    __half2 h = __float22half2_rn(make_float2(a, b));
    return *reinterpret_cast<unsigned*>(&h);
}
__device__ __forceinline__ float ex2(float x) {
    float y; asm("ex2.approx.f32 %0, %1;" : "=f"(y) : "f"(x)); return y;
}
__device__ __forceinline__ void mma16(float* d, const unsigned* a, unsigned b0, unsigned b1) {
    asm volatile("mma.sync.aligned.m16n8k16.row.col.f32.f16.f16.f32 "
                 "{%0,%1,%2,%3},{%4,%5,%6,%7},{%8,%9},{%0,%1,%2,%3};"
                 : "+f"(d[0]), "+f"(d[1]), "+f"(d[2]), "+f"(d[3])
                 : "r"(a[0]), "r"(a[1]), "r"(a[2]), "r"(a[3]), "r"(b0), "r"(b1));
}
__device__ __forceinline__ int aswz(int L) { return L ^ (L >> 3); }
// A-frag u32 address within a 64row x 64k block (4x4 tiles of 132 u, swizzled)
__device__ __forceinline__ int a_addr(int row, int k) {    // k even
    return ((row >> 4)*4 + (k >> 4)) * 132
         + aswz(((row & 7) << 2) | ((k >> 1) & 3)) * 4
         + ((row >> 3) & 1) + (((k >> 3) & 1) << 1);
}
__device__ __forceinline__ int bf_idx(int k, int n) {      // k even
    return ((((n & 7) << 2) | ((k >> 1) & 3)) << 1) + ((k >> 3) & 1);
}
__device__ __forceinline__ void bar64(int id) {
    asm volatile("bar.sync %0, %1;" :: "r"(id), "r"(64) : "memory");
}

// ---------------------------------------------------------------------------
// Kernel 1 (prep): Wp_eff fold + weights -> fp16 B-frag layouts.
// 65536 threads: h-sum split across thread pairs, merged via shfl.
// ---------------------------------------------------------------------------
__global__ __launch_bounds__(256) void prep_kernel(const float* __restrict__ Wq,
                                                   const float* __restrict__ Wk,
                                                   const float* __restrict__ Wv,
                                                   const float* __restrict__ Wp) {
    int idx2 = blockIdx.x * 256 + threadIdx.x;     // 0..65535
    int pid = idx2 >> 1, hh = idx2 & 1;
    {   // Wp_eff[d][j] = sum_h Wp[h*64+d][j];  each thread sums 8 h's
        int d0 = (pid >> 10) * 2, j = pid & 1023;
        float s0 = 0.f, s1 = 0.f;
#pragma unroll
        for (int h = hh*8; h < hh*8 + 8; h++) {
            s0 += Wp[(h*64 + d0    )*1024 + j];
            s1 += Wp[(h*64 + d0 + 1)*1024 + j];
        }
        s0 += __shfl_xor_sync(0xffffffffu, s0, 1);
        s1 += __shfl_xor_sync(0xffffffffu, s1, 1);
        if (!hh)
            g_wpef[(j >> 3)*256 + (d0 >> 4)*64 + bf_idx(d0, j)] = f2h2(s0, s1);
    }
    {   // W frags: k=c (pair), n=head dim
        const float qs = 0.03125f * 1.44269504088896f;
        int c0 = (pid >> 6) * 2, n = pid & 63;
        int ba = (c0 >> 4)*1536 + (n >> 3)*64 + bf_idx(c0, n);
        if (!hh) {
            g_wqkvf[ba]        = f2h2(Wq[c0*64 + n]*qs, Wq[(c0+1)*64 + n]*qs);
            g_wqkvf[ba + 512]  = f2h2(Wk[c0*64 + n],    Wk[(c0+1)*64 + n]);
        } else {
            g_wqkvf[ba + 1024] = f2h2(Wv[c0*64 + n],    Wv[(c0+1)*64 + n]);
        }
    }
}

// ---------------------------------------------------------------------------
// Kernel 2: fused QKV (unchanged from R7).
// ---------------------------------------------------------------------------
__global__ __launch_bounds__(256, 2) void qkv_kernel(const float* __restrict__ x) {
    extern __shared__ unsigned smu[];
    const int t = threadIdx.x, lane = t & 31, w = t >> 5;
    const int rowBase = blockIdx.x * 64;
    const int m0t = (w & 1) * 2;
    const int ntb = (w >> 1) * 6;

    float acc[2][6][4];
#pragma unroll
    for (int mi = 0; mi < 2; mi++)
#pragma unroll
        for (int ni = 0; ni < 6; ni++)
#pragma unroll
            for (int r = 0; r < 4; r++) acc[mi][ni][r] = 0.f;

    const int arow = t >> 2, acol4 = (t & 3) * 4;
    float4 xr[4];
#pragma unroll
    for (int q = 0; q < 4; q++)
        xr[q] = *(const float4*)&x[(size_t)(rowBase + arow)*CC + q*16 + acol4];
#pragma unroll
    for (int q = 0; q < 4; q++) {
        int k = q*16 + acol4;
        smu[a_addr(arow, k)]     = f2h2(xr[q].x, xr[q].y);
        smu[a_addr(arow, k + 2)] = f2h2(xr[q].z, xr[q].w);
    }
    __syncthreads();

    for (int k0 = 0; k0 < CC; k0 += 64) {
        const unsigned* As = smu + ((k0 >> 6) & 1) * 2112;
        const int ktG = k0 >> 4;
        const bool more = (k0 + 64) < CC;
        if (more) {
#pragma unroll
            for (int q = 0; q < 4; q++)
                xr[q] = *(const float4*)&x[(size_t)(rowBase + arow)*CC + k0 + 64 + q*16 + acol4];
        }
#pragma unroll
        for (int ks = 0; ks < 4; ks++) {
            uint4 v0 = *(const uint4*)&As[(m0t*4 + ks)*132 + aswz(lane)*4];
            uint4 v1 = *(const uint4*)&As[((m0t+1)*4 + ks)*132 + aswz(lane)*4];
            unsigned a0[4] = {v0.x, v0.y, v0.z, v0.w};
            unsigned a1[4] = {v1.x, v1.y, v1.z, v1.w};
#pragma unroll
            for (int ni = 0; ni < 6; ni++) {
                uint2 b = *(const uint2*)&g_wqkvf[(ktG + ks)*1536 + (ntb + ni)*64 + 2*lane];
                mma16(acc[0][ni], a0, b.x, b.y);
                mma16(acc[1][ni], a1, b.x, b.y);
            }
        }
        if (more) {
            unsigned* An = smu + (((k0 >> 6) & 1) ^ 1) * 2112;
#pragma unroll
            for (int q = 0; q < 4; q++) {
                int k = q*16 + acol4;
                An[a_addr(arow, k)]     = f2h2(xr[q].x, xr[q].y);
                An[a_addr(arow, k + 2)] = f2h2(xr[q].z, xr[q].w);
            }
        }
        __syncthreads();
    }

    // ---- epilogue: stage C-frags into fp16 operand layouts ----
    __half* vstage = (__half*)(smu + 6272);
#pragma unroll
    for (int mi = 0; mi < 2; mi++) {
#pragma unroll
        for (int ni = 0; ni < 6; ni++) {
            int row0 = (w & 1)*32 + mi*16 + (lane >> 2);
            int col0 = (ntb + ni)*8 + 2*(lane & 3);
            int mat = col0 >> 6;
            if (mat == 0) {
                smu[a_addr(row0,     col0)] = f2h2(acc[mi][ni][0], acc[mi][ni][1]);
                smu[a_addr(row0 + 8, col0)] = f2h2(acc[mi][ni][2], acc[mi][ni][3]);
            } else if (mat == 1) {
                int d = col0 - 64;
                int t0 = ((row0 >> 3)*4 + (d >> 4))*64;
                smu[4224 + t0       + bf_idx(d, row0)] = f2h2(acc[mi][ni][0], acc[mi][ni][1]);
                smu[4224 + t0 + 256 + bf_idx(d, row0)] = f2h2(acc[mi][ni][2], acc[mi][ni][3]);
            } else {
                int d = col0 - 128;
                int u0 = (d >> 3)*256 + (row0 >> 4)*64;
                vstage[(u0 + bf_idx(row0 & 63, d))*2     + (row0 & 1)] = __float2half_rn(acc[mi][ni][0]);
                vstage[(u0 + bf_idx(row0 & 63, d+1))*2   + (row0 & 1)] = __float2half_rn(acc[mi][ni][1]);
                int r8 = row0 + 8;
                int u8 = (d >> 3)*256 + (r8 >> 4)*64;
                vstage[(u8 + bf_idx(r8 & 63, d))*2   + (r8 & 1)] = __float2half_rn(acc[mi][ni][2]);
                vstage[(u8 + bf_idx(r8 & 63, d+1))*2 + (r8 & 1)] = __float2half_rn(acc[mi][ni][3]);
            }
        }
    }
    __syncthreads();

    const size_t rb = blockIdx.x;
#pragma unroll
    for (int j = 0; j < 2; j++) {
        int tile = w*2 + j;
        uint4 v = *(const uint4*)&smu[tile*132 + aswz(lane)*4];
        *(uint4*)&g_qf[rb*2048 + tile*128 + lane*4] = v;
    }
#pragma unroll
    for (int j = 0; j < 2; j++) {
        int u = t + 256*j;
        *(uint4*)&g_kf[rb*2048 + 4*u] = *(const uint4*)&smu[4224 + 4*u];
    }
#pragma unroll
    for (int j = 0; j < 2; j++) {
        int u = t + 256*j;
        *(uint4*)&g_vf[rb*2048 + 4*u] = *(const uint4*)&smu[6272 + 4*u];
    }
}

// ---------------------------------------------------------------------------
// Kernel 3: causal flash attention, KV-SPLIT by tile parity (no-max softmax
// makes the split merge a pure addition, done later in proj).
// Block = (batch, pair, kvh): processes KV tiles {kvh, kvh+2, ...} for both
// q-tiles of pair (i, 31-i) -> uniform 16-17 iterations per block.
// Grid 256, 256 thr, 2 blocks/SM. Writes fp32 O/l partials to gmem.
// ---------------------------------------------------------------------------
__global__ __launch_bounds__(256, 2) void attn_kernel() {
    extern __shared__ unsigned smu[];
    // K bufs: 0/2048 ; V bufs: 4096/6144 ; lsh @8192 (128 f); scr reuses K/V
    float* lsh = (float*)(smu + 8192);
    float* scr = (float*)smu;

    const int t = threadIdx.x, lane = t & 31, w = t >> 5;
    const int kvh   = blockIdx.x & 1;
    const int pair  = (blockIdx.x >> 1) & 15;
    const int batch = blockIdx.x >> 5;
    const int half_id = w & 1;
    const int mt = w >> 1;
    const int rl = lane >> 2;
    const int rA = mt*16 + rl, rB = rA + 8;
    const int colb = half_id * 32;
    const int barid = 1 + mt;
    float2* gop = kvh ? g_op1 : g_op0;
    float*  glp = kvh ? g_lp1 : g_lp0;

    for (int hh = 0; hh < 2; hh++) {
        const int qt = hh ? (31 - pair) : pair;
        const size_t qrb = batch*32 + qt;
        const int nit = (qt >= kvh) ? ((qt - kvh) >> 1) + 1 : 0;

        // Q fragments: gmem -> registers (4 k16 tiles)
        unsigned qf[4][4];
#pragma unroll
        for (int kt = 0; kt < 4; kt++) {
            uint4 v = *(const uint4*)&g_qf[qrb*2048 + (mt*4 + kt)*128 + lane*4];
            qf[kt][0] = v.x; qf[kt][1] = v.y; qf[kt][2] = v.z; qf[kt][3] = v.w;
        }

        float lAr = 0.f, lBr = 0.f;
        float oacc[8][4];
#pragma unroll
        for (int ni = 0; ni < 8; ni++)
#pragma unroll
            for (int r = 0; r < 4; r++) oacc[ni][r] = 0.f;

        uint4 kr[2], vr[2];
        if (nit > 0) {       // prefetch + store first tile (index kvh)
            size_t tb = batch*32 + kvh;
#pragma unroll
            for (int j = 0; j < 2; j++) {
                kr[j] = *(const uint4*)&g_kf[tb*2048 + 4*(t + 256*j)];
                vr[j] = *(const uint4*)&g_vf[tb*2048 + 4*(t + 256*j)];
            }
#pragma unroll
            for (int j = 0; j < 2; j++) {
                *(uint4*)&smu[4*(t + 256*j)]        = kr[j];
                *(uint4*)&smu[4096 + 4*(t + 256*j)] = vr[j];
            }
        }
        __syncthreads();

        for (int ii = 0; ii < nit; ii++) {
            const int it = kvh + 2*ii;
            const unsigned* Kb = smu + (ii & 1)*2048;
            const unsigned* Vb = smu + 4096 + (ii & 1)*2048;

            // S' = Q @ K^T (log2e folded into q)
            float sacc[4][4];
#pragma unroll
            for (int ni = 0; ni < 4; ni++)
#pragma unroll
                for (int r = 0; r < 4; r++) sacc[ni][r] = 0.f;
#pragma unroll
            for (int ks = 0; ks < 4; ks++)
#pragma unroll
                for (int ni = 0; ni < 4; ni++) {
                    uint2 b = *(const uint2*)&Kb[((half_id*4 + ni)*4 + ks)*64 + 2*lane];
                    mma16(sacc[ni], qf[ks], b.x, b.y);
                }

            // prefetch next tile (it + 2)
            const bool more = (ii + 1) < nit;
            if (more) {
                size_t tb = batch*32 + it + 2;
#pragma unroll
                for (int j = 0; j < 2; j++) {
                    kr[j] = *(const uint4*)&g_kf[tb*2048 + 4*(t + 256*j)];
                    vr[j] = *(const uint4*)&g_vf[tb*2048 + 4*(t + 256*j)];
                }
            }

            // causal mask on diagonal tile
            if (it == qt) {
#pragma unroll
                for (int ni = 0; ni < 4; ni++) {
                    int c0 = colb + ni*8 + 2*(lane & 3);
                    if (c0     > rA) sacc[ni][0] = -1e30f;
                    if (c0 + 1 > rA) sacc[ni][1] = -1e30f;
                    if (c0     > rB) sacc[ni][2] = -1e30f;
                    if (c0 + 1 > rB) sacc[ni][3] = -1e30f;
                }
            }

            // P = 2^S' into A-fragment registers (C-frag == A-frag map)
            unsigned pa[2][4];
#pragma unroll
            for (int ni = 0; ni < 4; ni++) {
                float p0 = ex2(sacc[ni][0]);
                float p1 = ex2(sacc[ni][1]);
                float p2 = ex2(sacc[ni][2]);
                float p3 = ex2(sacc[ni][3]);
                lAr += p0 + p1;
                lBr += p2 + p3;
                pa[ni >> 1][(ni & 1)*2]     = f2h2(p0, p1);
                pa[ni >> 1][(ni & 1)*2 + 1] = f2h2(p2, p3);
            }

            // O += P @ V over own 32 keys (2 key16 tiles), all 64 d-cols
#pragma unroll
            for (int p = 0; p < 2; p++)
#pragma unroll
                for (int ni = 0; ni < 8; ni++) {
                    uint2 b = *(const uint2*)&Vb[(ni*4 + half_id*2 + p)*64 + 2*lane];
                    mma16(oacc[ni], pa[p], b.x, b.y);
                }

            if (more) {
                unsigned nb = ((ii + 1) & 1) * 2048;
#pragma unroll
                for (int j = 0; j < 2; j++) {
                    *(uint4*)&smu[nb + 4*(t + 256*j)]        = kr[j];
                    *(uint4*)&smu[4096 + nb + 4*(t + 256*j)] = vr[j];
                }
            }
            __syncthreads();
        }

        // ---- merge column halves (addition only) and write fp32 partials ----
        lAr += __shfl_xor_sync(0xffffffffu, lAr, 1);
        lAr += __shfl_xor_sync(0xffffffffu, lAr, 2);
        lBr += __shfl_xor_sync(0xffffffffu, lBr, 1);
        lBr += __shfl_xor_sync(0xffffffffu, lBr, 2);
        if ((lane & 3) == 0) {
            lsh[rA*2 + half_id] = lAr;
            lsh[rB*2 + half_id] = lBr;
        }
        bar64(barid);
        float lA = lsh[rA*2] + lsh[rA*2 + 1];
        float lB = lsh[rB*2] + lsh[rB*2 + 1];

        float* sc = scr + mt*1024;
        if (half_id) {
#pragma unroll
            for (int ni = 0; ni < 8; ni++) {
                sc[(ni*4 + 0)*32 + lane] = oacc[ni][0];
                sc[(ni*4 + 1)*32 + lane] = oacc[ni][1];
                sc[(ni*4 + 2)*32 + lane] = oacc[ni][2];
                sc[(ni*4 + 3)*32 + lane] = oacc[ni][3];
            }
        }
        bar64(barid);
        if (!half_id) {
#pragma unroll
            for (int ni = 0; ni < 8; ni++) {
                float o0 = oacc[ni][0] + sc[(ni*4 + 0)*32 + lane];
                float o1 = oacc[ni][1] + sc[(ni*4 + 1)*32 + lane];
                float o2 = oacc[ni][2] + sc[(ni*4 + 2)*32 + lane];
                float o3 = oacc[ni][3] + sc[(ni*4 + 3)*32 + lane];
                size_t slot = qrb*2048 + (mt*4 + (ni >> 1))*128 + lane*4 + ((ni & 1) << 1);
                gop[slot]     = make_float2(o0, o1);
                gop[slot + 1] = make_float2(o2, o3);
            }
            if ((lane & 3) == 0) {
                glp[qrb*64 + rA] = lA;
                glp[qrb*64 + rB] = lB;
            }
        }
        __syncthreads();     // protect scr (K/V region) before next hh phase
    }
}

// ---------------------------------------------------------------------------
// Kernel 4: merge kv-split partials, normalize, project:
// out = ((O0+O1)/(l0+l1)) @ Wp_eff + bp.
// B slice (16 KB) smem-resident; out tile staged in smem for coalesced
// float4 stores. Grid (8 colblocks x 64 rowgroups), 4 row-blocks each.
// ---------------------------------------------------------------------------
__global__ __launch_bounds__(256) void proj_kernel(float* __restrict__ out,
                                                   const float* __restrict__ bp) {
    extern __shared__ unsigned smu[];
    unsigned* Bs = smu;                 // 4096 u32: [ntLocal(16)][kt(4)][64]
    float* Os = (float*)(smu + 4096);   // 64 x 132 staging

    const int t = threadIdx.x, lane = t & 31, w = t >> 5;
    const int ntBase = blockIdx.x * 16;
    const int colBase = blockIdx.x * 128;
    const int mt = w & 3;
    const int ntb = (w >> 2) * 8;

#pragma unroll
    for (int j = 0; j < 4; j++) {
        int u = t + 256*j;
        *(uint4*)&Bs[4*u] = *(const uint4*)&g_wpef[(size_t)ntBase*256 + 4*u];
    }
    float2 bias[8];
#pragma unroll
    for (int ni = 0; ni < 8; ni++)
        bias[ni] = *(const float2*)&bp[colBase + (ntb + ni)*8 + 2*(lane & 3)];
    __syncthreads();

    const size_t rb0 = (size_t)blockIdx.y * 4;
    const int rowA = mt*16 + (lane >> 2);
    const int rowB = rowA + 8;

    for (int i = 0; i < 4; i++) {
        const size_t rb = rb0 + i;

        // merge partials -> fp16 A-fragments
        float invA = 1.0f / (g_lp0[rb*64 + rowA] + g_lp1[rb*64 + rowA]);
        float invB = 1.0f / (g_lp0[rb*64 + rowB] + g_lp1[rb*64 + rowB]);
        unsigned a[4][4];
#pragma unroll
        for (int kt = 0; kt < 4; kt++) {
            size_t base = rb*2048 + (mt*4 + kt)*128 + lane*4;
#pragma unroll
            for (int e = 0; e < 4; e++) {
                float2 p0 = g_op0[base + e];
                float2 p1 = g_op1[base + e];
                float iv = (e & 1) ? invB : invA;
                a[kt][e] = f2h2((p0.x + p1.x)*iv, (p0.y + p1.y)*iv);
            }
        }

        float acc[8][4];
#pragma unroll
        for (int ni = 0; ni < 8; ni++)
#pragma unroll
            for (int r = 0; r < 4; r++) acc[ni][r] = 0.f;
#pragma unroll
        for (int kt = 0; kt < 4; kt++)
#pragma unroll
            for (int ni = 0; ni < 8; ni++) {
                uint2 b = *(const uint2*)&Bs[((ntb + ni)*4 + kt)*64 + 2*lane];
                mma16(acc[ni], a[kt], b.x, b.y);
            }

        // stage out tile (with bias) for coalesced stores
#pragma unroll
        for (int ni = 0; ni < 8; ni++) {
            int col = (ntb + ni)*8 + 2*(lane & 3);
            *(float2*)&Os[rowA*132 + col] =
                make_float2(acc[ni][0] + bias[ni].x, acc[ni][1] + bias[ni].y);
            *(float2*)&Os[rowB*132 + col] =
                make_float2(acc[ni][2] + bias[ni].x, acc[ni][3] + bias[ni].y);
        }
        __syncthreads();
#pragma unroll
        for (int j = 0; j < 8; j++) {
            int u = t + 256*j;             // 0..2047 float4s
            int row = u >> 5, c4 = (u & 31)*4;
            float4 v = *(const float4*)&Os[row*132 + c4];
            *(float4*)&out[(size_t)(rb*64 + row)*CC + colBase + c4] = v;
        }
        __syncthreads();
    }
}

// ---------------------------------------------------------------------------
// Launch
// ---------------------------------------------------------------------------
extern "C" void kernel_launch(void* const* d_in, const int* in_sizes, int n_in,
                              void* d_out, int out_size) {
    const float* x  = (const float*)d_in[0];
    const float* Wq = (const float*)d_in[1];
    const float* Wk = (const float*)d_in[2];
    const float* Wv = (const float*)d_in[3];
    const float* Wp = (const float*)d_in[4];
    const float* bp = (const float*)d_in[5];
    float* out = (float*)d_out;

    const int qkv_smem  = 8320 * 4;            // 33280 B
    const int attn_smem = 8320 * 4;            // 33280 B (K/V bufs + lsh)
    const int proj_smem = (4096 + 8448) * 4;   // 50176 B

    cudaFuncSetAttribute(qkv_kernel,  cudaFuncAttributeMaxDynamicSharedMemorySize, qkv_smem);
    cudaFuncSetAttribute(attn_kernel, cudaFuncAttributeMaxDynamicSharedMemorySize, attn_smem);
    cudaFuncSetAttribute(proj_kernel, cudaFuncAttributeMaxDynamicSharedMemorySize, proj_smem);

    prep_kernel<<<256, 256>>>(Wq, Wk, Wv, Wp);
    qkv_kernel<<<MM/64, 256, qkv_smem>>>(x);
    attn_kernel<<<256, 256, attn_smem>>>();
    proj_kernel<<<dim3(8, 64), 256, proj_smem>>>(out, bp);
}

// round 10
// speedup vs baseline: 1.3339x; 1.3339x over previous
#include <cuda_runtime.h>
#include <cuda_fp16.h>
#include <math.h>

// Problem constants
#define BB 8
#define TT 2048
#define CC 1024
#define DD 64
#define MM (BB*TT)          // 16384 rows

// ---------------------------------------------------------------------------
// Global scratch, all fp16 fragment layouts (allocation-free __device__)
// A-frag (m16k16, 128 u32/tile); B-frag (k16n8, 64 u32/tile)
// ---------------------------------------------------------------------------
__device__ unsigned g_qf [MM*DD/2];   // q,  A-frag per 64-token block (scale*log2e folded)
__device__ unsigned g_kf [MM*DD/2];   // k,  B-frag: [tb][(keyTile8)(dTile4)][64]   (k=d,n=key)
__device__ unsigned g_vf [MM*DD/2];   // v,  B-frag: [tb][(dTile8)(keyTile4)][64]   (k=key,n=d)
__device__ unsigned g_hof[MM*DD/2];   // head_out, A-frag per 64-token block
__device__ unsigned g_wpef[DD*CC/2];      // Wp_eff: [nt(128)][kt(4)][64]
__device__ unsigned g_wqkvf[3*CC*DD/2];   // W q|k|v: [ktG(64)][mat*8+nt(24)][64]

// ---------------------------------------------------------------------------
// helpers
// ---------------------------------------------------------------------------
__device__ __forceinline__ unsigned f2h2(float a, float b) {
    __half2 h = __float22half2_rn(make_float2(a, b));
    return *reinterpret_cast<unsigned*>(&h);
}
__device__ __forceinline__ float ex2(float x) {
    float y; asm("ex2.approx.f32 %0, %1;" : "=f"(y) : "f"(x)); return y;
}
__device__ __forceinline__ void mma16(float* d, const unsigned* a, unsigned b0, unsigned b1) {
    asm volatile("mma.sync.aligned.m16n8k16.row.col.f32.f16.f16.f32 "
                 "{%0,%1,%2,%3},{%4,%5,%6,%7},{%8,%9},{%0,%1,%2,%3};"
                 : "+f"(d[0]), "+f"(d[1]), "+f"(d[2]), "+f"(d[3])
                 : "r"(a[0]), "r"(a[1]), "r"(a[2]), "r"(a[3]), "r"(b0), "r"(b1));
}
__device__ __forceinline__ int aswz(int L) { return L ^ (L >> 3); }
// A-frag u32 address within a 64row x 64k block (4x4 tiles of 132 u, swizzled)
__device__ __forceinline__ int a_addr(int row, int k) {    // k even
    return ((row >> 4)*4 + (k >> 4)) * 132
         + aswz(((row & 7) << 2) | ((k >> 1) & 3)) * 4
         + ((row >> 3) & 1) + (((k >> 3) & 1) << 1);
}
__device__ __forceinline__ int bf_idx(int k, int n) {      // k even
    return ((((n & 7) << 2) | ((k >> 1) & 3)) << 1) + ((k >> 3) & 1);
}
__device__ __forceinline__ void bar64(int id) {
    asm volatile("bar.sync %0, %1;" :: "r"(id), "r"(64) : "memory");
}

// ---------------------------------------------------------------------------
// Kernel 1 (prep): Wp_eff fold + weights -> fp16 B-frag layouts.
// 65536 threads: h-sum split across thread pairs, merged via shfl.
// ---------------------------------------------------------------------------
__global__ __launch_bounds__(256) void prep_kernel(const float* __restrict__ Wq,
                                                   const float* __restrict__ Wk,
                                                   const float* __restrict__ Wv,
                                                   const float* __restrict__ Wp) {
    int idx2 = blockIdx.x * 256 + threadIdx.x;     // 0..65535
    int pid = idx2 >> 1, hh = idx2 & 1;
    {   // Wp_eff[d][j] = sum_h Wp[h*64+d][j];  each thread sums 8 h's
        int d0 = (pid >> 10) * 2, j = pid & 1023;
        float s0 = 0.f, s1 = 0.f;
#pragma unroll
        for (int h = hh*8; h < hh*8 + 8; h++) {
            s0 += Wp[(h*64 + d0    )*1024 + j];
            s1 += Wp[(h*64 + d0 + 1)*1024 + j];
        }
        s0 += __shfl_xor_sync(0xffffffffu, s0, 1);
        s1 += __shfl_xor_sync(0xffffffffu, s1, 1);
        if (!hh)
            g_wpef[(j >> 3)*256 + (d0 >> 4)*64 + bf_idx(d0, j)] = f2h2(s0, s1);
    }
    {   // W frags: k=c (pair), n=head dim
        const float qs = 0.03125f * 1.44269504088896f;
        int c0 = (pid >> 6) * 2, n = pid & 63;
        int ba = (c0 >> 4)*1536 + (n >> 3)*64 + bf_idx(c0, n);
        if (!hh) {
            g_wqkvf[ba]        = f2h2(Wq[c0*64 + n]*qs, Wq[(c0+1)*64 + n]*qs);
            g_wqkvf[ba + 512]  = f2h2(Wk[c0*64 + n],    Wk[(c0+1)*64 + n]);
        } else {
            g_wqkvf[ba + 1024] = f2h2(Wv[c0*64 + n],    Wv[(c0+1)*64 + n]);
        }
    }
}

// ---------------------------------------------------------------------------
// Kernel 2: fused QKV (unchanged from R7 / 81.9us version).
// ---------------------------------------------------------------------------
__global__ __launch_bounds__(256, 2) void qkv_kernel(const float* __restrict__ x) {
    extern __shared__ unsigned smu[];
    const int t = threadIdx.x, lane = t & 31, w = t >> 5;
    const int rowBase = blockIdx.x * 64;
    const int m0t = (w & 1) * 2;
    const int ntb = (w >> 1) * 6;

    float acc[2][6][4];
#pragma unroll
    for (int mi = 0; mi < 2; mi++)
#pragma unroll
        for (int ni = 0; ni < 6; ni++)
#pragma unroll
            for (int r = 0; r < 4; r++) acc[mi][ni][r] = 0.f;

    const int arow = t >> 2, acol4 = (t & 3) * 4;
    float4 xr[4];
#pragma unroll
    for (int q = 0; q < 4; q++)
        xr[q] = *(const float4*)&x[(size_t)(rowBase + arow)*CC + q*16 + acol4];
#pragma unroll
    for (int q = 0; q < 4; q++) {
        int k = q*16 + acol4;
        smu[a_addr(arow, k)]     = f2h2(xr[q].x, xr[q].y);
        smu[a_addr(arow, k + 2)] = f2h2(xr[q].z, xr[q].w);
    }
    __syncthreads();

    for (int k0 = 0; k0 < CC; k0 += 64) {
        const unsigned* As = smu + ((k0 >> 6) & 1) * 2112;
        const int ktG = k0 >> 4;
        const bool more = (k0 + 64) < CC;
        if (more) {
#pragma unroll
            for (int q = 0; q < 4; q++)
                xr[q] = *(const float4*)&x[(size_t)(rowBase + arow)*CC + k0 + 64 + q*16 + acol4];
        }
#pragma unroll
        for (int ks = 0; ks < 4; ks++) {
            uint4 v0 = *(const uint4*)&As[(m0t*4 + ks)*132 + aswz(lane)*4];
            uint4 v1 = *(const uint4*)&As[((m0t+1)*4 + ks)*132 + aswz(lane)*4];
            unsigned a0[4] = {v0.x, v0.y, v0.z, v0.w};
            unsigned a1[4] = {v1.x, v1.y, v1.z, v1.w};
#pragma unroll
            for (int ni = 0; ni < 6; ni++) {
                uint2 b = *(const uint2*)&g_wqkvf[(ktG + ks)*1536 + (ntb + ni)*64 + 2*lane];
                mma16(acc[0][ni], a0, b.x, b.y);
                mma16(acc[1][ni], a1, b.x, b.y);
            }
        }
        if (more) {
            unsigned* An = smu + (((k0 >> 6) & 1) ^ 1) * 2112;
#pragma unroll
            for (int q = 0; q < 4; q++) {
                int k = q*16 + acol4;
                An[a_addr(arow, k)]     = f2h2(xr[q].x, xr[q].y);
                An[a_addr(arow, k + 2)] = f2h2(xr[q].z, xr[q].w);
            }
        }
        __syncthreads();
    }

    // ---- epilogue: stage C-frags into fp16 operand layouts ----
    __half* vstage = (__half*)(smu + 6272);
#pragma unroll
    for (int mi = 0; mi < 2; mi++) {
#pragma unroll
        for (int ni = 0; ni < 6; ni++) {
            int row0 = (w & 1)*32 + mi*16 + (lane >> 2);
            int col0 = (ntb + ni)*8 + 2*(lane & 3);
            int mat = col0 >> 6;
            if (mat == 0) {
                smu[a_addr(row0,     col0)] = f2h2(acc[mi][ni][0], acc[mi][ni][1]);
                smu[a_addr(row0 + 8, col0)] = f2h2(acc[mi][ni][2], acc[mi][ni][3]);
            } else if (mat == 1) {
                int d = col0 - 64;
                int t0 = ((row0 >> 3)*4 + (d >> 4))*64;
                smu[4224 + t0       + bf_idx(d, row0)] = f2h2(acc[mi][ni][0], acc[mi][ni][1]);
                smu[4224 + t0 + 256 + bf_idx(d, row0)] = f2h2(acc[mi][ni][2], acc[mi][ni][3]);
            } else {
                int d = col0 - 128;
                int u0 = (d >> 3)*256 + (row0 >> 4)*64;
                vstage[(u0 + bf_idx(row0 & 63, d))*2     + (row0 & 1)] = __float2half_rn(acc[mi][ni][0]);
                vstage[(u0 + bf_idx(row0 & 63, d+1))*2   + (row0 & 1)] = __float2half_rn(acc[mi][ni][1]);
                int r8 = row0 + 8;
                int u8 = (d >> 3)*256 + (r8 >> 4)*64;
                vstage[(u8 + bf_idx(r8 & 63, d))*2   + (r8 & 1)] = __float2half_rn(acc[mi][ni][2]);
                vstage[(u8 + bf_idx(r8 & 63, d+1))*2 + (r8 & 1)] = __float2half_rn(acc[mi][ni][3]);
            }
        }
    }
    __syncthreads();

    const size_t rb = blockIdx.x;
#pragma unroll
    for (int j = 0; j < 2; j++) {
        int tile = w*2 + j;
        uint4 v = *(const uint4*)&smu[tile*132 + aswz(lane)*4];
        *(uint4*)&g_qf[rb*2048 + tile*128 + lane*4] = v;
    }
#pragma unroll
    for (int j = 0; j < 2; j++) {
        int u = t + 256*j;
        *(uint4*)&g_kf[rb*2048 + 4*u] = *(const uint4*)&smu[4224 + 4*u];
    }
#pragma unroll
    for (int j = 0; j < 2; j++) {
        int u = t + 256*j;
        *(uint4*)&g_vf[rb*2048 + 4*u] = *(const uint4*)&smu[6272 + 4*u];
    }
}

// ---------------------------------------------------------------------------
// Kernel 3: causal flash attention (R7 numerics: no-max softmax, register P,
// deferred l reduction, 1 sync per KV tile).
// UNPAIRED grid: 256 blocks, one q-tile each, qt descending with bid so the
// 32-iteration blocks launch in wave 1 (LPT schedule over all 148 SMs).
// ---------------------------------------------------------------------------
__global__ __launch_bounds__(256, 1) void attn_kernel() {
    extern __shared__ unsigned smu[];
    // K bufs: 0/2048 ; V bufs: 4096/6144 ; ho staging Ps: 8192 (2112 u)
    // lsh @10304 (128 f) ; merge scratch reuses K/V area
    unsigned* Ps = smu + 8192;
    float* lsh = (float*)(smu + 10304);
    float* scr = (float*)smu;

    const int t = threadIdx.x, lane = t & 31, w = t >> 5;
    const int bid = blockIdx.x;
    const int batch = bid & 7;
    const int qt = 31 - (bid >> 3);       // big q-tiles first
    const int half_id = w & 1;
    const int mt = w >> 1;
    const int rl = lane >> 2;
    const int rA = mt*16 + rl, rB = rA + 8;
    const int colb = half_id * 32;
    const int barid = 1 + mt;

    const size_t qrb = batch*32 + qt;
    const int ntiles = qt + 1;

    // Q fragments: gmem -> registers (4 k16 tiles)
    unsigned qf[4][4];
#pragma unroll
    for (int kt = 0; kt < 4; kt++) {
        uint4 v = *(const uint4*)&g_qf[qrb*2048 + (mt*4 + kt)*128 + lane*4];
        qf[kt][0] = v.x; qf[kt][1] = v.y; qf[kt][2] = v.z; qf[kt][3] = v.w;
    }
    // prefetch + store KV tile 0
    uint4 kr[2], vr[2];
    {
        size_t tb = batch*32;
#pragma unroll
        for (int j = 0; j < 2; j++) {
            kr[j] = *(const uint4*)&g_kf[tb*2048 + 4*(t + 256*j)];
            vr[j] = *(const uint4*)&g_vf[tb*2048 + 4*(t + 256*j)];
        }
    }
#pragma unroll
    for (int j = 0; j < 2; j++) {
        *(uint4*)&smu[4*(t + 256*j)]        = kr[j];
        *(uint4*)&smu[4096 + 4*(t + 256*j)] = vr[j];
    }

    float lAr = 0.f, lBr = 0.f;
    float oacc[8][4];
#pragma unroll
    for (int ni = 0; ni < 8; ni++)
#pragma unroll
        for (int r = 0; r < 4; r++) oacc[ni][r] = 0.f;
    __syncthreads();

    for (int it = 0; it < ntiles; it++) {
        const unsigned* Kb = smu + (it & 1)*2048;
        const unsigned* Vb = smu + 4096 + (it & 1)*2048;

        // S' = Q @ K^T (log2e folded into q)
        float sacc[4][4];
#pragma unroll
        for (int ni = 0; ni < 4; ni++)
#pragma unroll
            for (int r = 0; r < 4; r++) sacc[ni][r] = 0.f;
#pragma unroll
        for (int ks = 0; ks < 4; ks++)
#pragma unroll
            for (int ni = 0; ni < 4; ni++) {
                uint2 b = *(const uint2*)&Kb[((half_id*4 + ni)*4 + ks)*64 + 2*lane];
                mma16(sacc[ni], qf[ks], b.x, b.y);
            }

        // prefetch next KV tile
        const bool more = (it + 1) < ntiles;
        if (more) {
            size_t tb = batch*32 + it + 1;
#pragma unroll
            for (int j = 0; j < 2; j++) {
                kr[j] = *(const uint4*)&g_kf[tb*2048 + 4*(t + 256*j)];
                vr[j] = *(const uint4*)&g_vf[tb*2048 + 4*(t + 256*j)];
            }
        }

        // causal mask on diagonal tile
        if (it == ntiles - 1) {
#pragma unroll
            for (int ni = 0; ni < 4; ni++) {
                int c0 = colb + ni*8 + 2*(lane & 3);
                if (c0     > rA) sacc[ni][0] = -1e30f;
                if (c0 + 1 > rA) sacc[ni][1] = -1e30f;
                if (c0     > rB) sacc[ni][2] = -1e30f;
                if (c0 + 1 > rB) sacc[ni][3] = -1e30f;
            }
        }

        // P = 2^S' directly into A-fragment registers (C-frag == A-frag map)
        unsigned pa[2][4];
#pragma unroll
        for (int ni = 0; ni < 4; ni++) {
            float p0 = ex2(sacc[ni][0]);
            float p1 = ex2(sacc[ni][1]);
            float p2 = ex2(sacc[ni][2]);
            float p3 = ex2(sacc[ni][3]);
            lAr += p0 + p1;
            lBr += p2 + p3;
            pa[ni >> 1][(ni & 1)*2]     = f2h2(p0, p1);
            pa[ni >> 1][(ni & 1)*2 + 1] = f2h2(p2, p3);
        }

        // O += P @ V over own 32 keys (2 key16 tiles), all 64 d-cols
#pragma unroll
        for (int p = 0; p < 2; p++)
#pragma unroll
            for (int ni = 0; ni < 8; ni++) {
                uint2 b = *(const uint2*)&Vb[(ni*4 + half_id*2 + p)*64 + 2*lane];
                mma16(oacc[ni], pa[p], b.x, b.y);
            }

        // store next KV tile into other buffer
        if (more) {
            unsigned nb = ((it + 1) & 1) * 2048;
#pragma unroll
            for (int j = 0; j < 2; j++) {
                *(uint4*)&smu[nb + 4*(t + 256*j)]        = kr[j];
                *(uint4*)&smu[4096 + nb + 4*(t + 256*j)] = vr[j];
            }
        }
        __syncthreads();
    }

    // ---- reduce l across lanes, then merge the two column halves ----
    lAr += __shfl_xor_sync(0xffffffffu, lAr, 1);
    lAr += __shfl_xor_sync(0xffffffffu, lAr, 2);
    lBr += __shfl_xor_sync(0xffffffffu, lBr, 1);
    lBr += __shfl_xor_sync(0xffffffffu, lBr, 2);
    if ((lane & 3) == 0) {
        lsh[rA*2 + half_id] = lAr;
        lsh[rB*2 + half_id] = lBr;
    }
    bar64(barid);
    float iA = 1.0f / (lsh[rA*2] + lsh[rA*2 + 1]);
    float iB = 1.0f / (lsh[rB*2] + lsh[rB*2 + 1]);

    float* sc = scr + mt*1024;
    if (half_id) {
#pragma unroll
        for (int ni = 0; ni < 8; ni++) {
            sc[(ni*4 + 0)*32 + lane] = oacc[ni][0];
            sc[(ni*4 + 1)*32 + lane] = oacc[ni][1];
            sc[(ni*4 + 2)*32 + lane] = oacc[ni][2];
            sc[(ni*4 + 3)*32 + lane] = oacc[ni][3];
        }
    }
    bar64(barid);
    if (!half_id) {
#pragma unroll
        for (int ni = 0; ni < 8; ni++) {
            int d0 = ni*8 + 2*(lane & 3);
            float v0 = (oacc[ni][0] + sc[(ni*4 + 0)*32 + lane]) * iA;
            float v1 = (oacc[ni][1] + sc[(ni*4 + 1)*32 + lane]) * iA;
            float v2 = (oacc[ni][2] + sc[(ni*4 + 2)*32 + lane]) * iB;
            float v3 = (oacc[ni][3] + sc[(ni*4 + 3)*32 + lane]) * iB;
            Ps[a_addr(mt*16 + rl,     d0)] = f2h2(v0, v1);
            Ps[a_addr(mt*16 + rl + 8, d0)] = f2h2(v2, v3);
        }
    }
    __syncthreads();
#pragma unroll
    for (int j = 0; j < 2; j++) {
        int tile = w*2 + j;
        uint4 v = *(const uint4*)&Ps[tile*132 + aswz(lane)*4];
        *(uint4*)&g_hof[qrb*2048 + tile*128 + lane*4] = v;
    }
}

// ---------------------------------------------------------------------------
// Kernel 4: out = ho @ Wp_eff + bp (unchanged from R7 / 81.9us version).
// B slice (16 KB) resident in smem; 4 row-blocks per block with A prefetch.
// Grid (8 colblocks x 64 rowgroups) = 512 blocks.
// ---------------------------------------------------------------------------
__global__ __launch_bounds__(256) void proj_kernel(float* __restrict__ out,
                                                   const float* __restrict__ bp) {
    __shared__ unsigned Bs[4096];       // [ntLocal(16)][kt(4)][64]

    const int t = threadIdx.x, lane = t & 31, w = t >> 5;
    const int ntBase = blockIdx.x * 16;
    const int colBase = blockIdx.x * 128;
    const int mt = w & 3;
    const int ntb = (w >> 2) * 8;

#pragma unroll
    for (int j = 0; j < 4; j++) {
        int u = t + 256*j;              // 0..1023 (x4 u32)
        *(uint4*)&Bs[4*u] = *(const uint4*)&g_wpef[(size_t)ntBase*256 + 4*u];
    }
    float2 bias[8];
#pragma unroll
    for (int ni = 0; ni < 8; ni++)
        bias[ni] = *(const float2*)&bp[colBase + (ntb + ni)*8 + 2*(lane & 3)];
    __syncthreads();

    const size_t rb0 = (size_t)blockIdx.y * 4;
    uint4 a0[4];
#pragma unroll
    for (int ks = 0; ks < 4; ks++)
        a0[ks] = *(const uint4*)&g_hof[rb0*2048 + (mt*4 + ks)*128 + lane*4];

    for (int i = 0; i < 4; i++) {
        const size_t rb = rb0 + i;
        uint4 an[4];
        if (i < 3) {
#pragma unroll
            for (int ks = 0; ks < 4; ks++)
                an[ks] = *(const uint4*)&g_hof[(rb + 1)*2048 + (mt*4 + ks)*128 + lane*4];
        }

        float acc[8][4];
#pragma unroll
        for (int ni = 0; ni < 8; ni++)
#pragma unroll
            for (int r = 0; r < 4; r++) acc[ni][r] = 0.f;

#pragma unroll
        for (int ks = 0; ks < 4; ks++) {
            unsigned a[4] = {a0[ks].x, a0[ks].y, a0[ks].z, a0[ks].w};
#pragma unroll
            for (int ni = 0; ni < 8; ni++) {
                uint2 b = *(const uint2*)&Bs[((ntb + ni)*4 + ks)*64 + 2*lane];
                mma16(acc[ni], a, b.x, b.y);
            }
        }

        int row = (int)rb*64 + mt*16 + (lane >> 2);
#pragma unroll
        for (int ni = 0; ni < 8; ni++) {
            int col = colBase + (ntb + ni)*8 + 2*(lane & 3);
            *(float2*)&out[(size_t)row*CC + col] =
                make_float2(acc[ni][0] + bias[ni].x, acc[ni][1] + bias[ni].y);
            *(float2*)&out[(size_t)(row + 8)*CC + col] =
                make_float2(acc[ni][2] + bias[ni].x, acc[ni][3] + bias[ni].y);
        }
#pragma unroll
        for (int ks = 0; ks < 4; ks++) a0[ks] = an[ks];
    }
}

// ---------------------------------------------------------------------------
// Launch
// ---------------------------------------------------------------------------
extern "C" void kernel_launch(void* const* d_in, const int* in_sizes, int n_in,
                              void* d_out, int out_size) {
    const float* x  = (const float*)d_in[0];
    const float* Wq = (const float*)d_in[1];
    const float* Wk = (const float*)d_in[2];
    const float* Wv = (const float*)d_in[3];
    const float* Wp = (const float*)d_in[4];
    const float* bp = (const float*)d_in[5];
    float* out = (float*)d_out;

    const int qkv_smem  = 8320 * 4;    // 33280 B
    const int attn_smem = 10432 * 4;   // 41728 B

    cudaFuncSetAttribute(qkv_kernel,  cudaFuncAttributeMaxDynamicSharedMemorySize, qkv_smem);
    cudaFuncSetAttribute(attn_kernel, cudaFuncAttributeMaxDynamicSharedMemorySize, attn_smem);

    prep_kernel<<<256, 256>>>(Wq, Wk, Wv, Wp);
    qkv_kernel<<<MM/64, 256, qkv_smem>>>(x);
    attn_kernel<<<256, 256, attn_smem>>>();
    proj_kernel<<<dim3(8, 64), 256>>>(out, bp);
}